// round 17
// baseline (speedup 1.0000x reference)
#include <cuda_runtime.h>
#include <cuda_bf16.h>
#include <cstdint>

// S4D via per-head GEMM on mma.sync bf16 tensor cores.
//   K[h, 32m+j] = sum_k A[m,k]*B[j,k],  m<128, j<32, k<64
// R17 change: A-fragment rows within a thread are spaced 8 apart (dl0=256);
// instead of 16 transcendental starts per thread, compute 1 start per k-step
// and derive the other 3 rows by chained complex mul with E8 = z^256
// (precomputed per mode). MUFU per thread: 80 -> 32; A-gen packed ops halved.

typedef unsigned long long u64;
typedef unsigned int u32;

static constexpr int kH = 1024;
static constexpr int kN2 = 32;
static constexpr int kL = 4096;
static constexpr int kTPB = 128;
static constexpr int TABS = 36;   // smem table stride (words), conflict-free

// ---- packed f32x2 helpers ----
__device__ __forceinline__ u64 pk2(float lo, float hi) {
    u64 r; asm("mov.b64 %0, {%1, %2};" : "=l"(r) : "f"(lo), "f"(hi)); return r;
}
__device__ __forceinline__ void upk2(u64 v, float& lo, float& hi) {
    asm("mov.b64 {%0, %1}, %2;" : "=f"(lo), "=f"(hi) : "l"(v));
}
__device__ __forceinline__ u64 fma2(u64 a, u64 b, u64 c) {
    u64 r; asm("fma.rn.f32x2 %0, %1, %2, %3;" : "=l"(r) : "l"(a), "l"(b), "l"(c)); return r;
}
__device__ __forceinline__ u64 mul2(u64 a, u64 b) {
    u64 r; asm("mul.rn.f32x2 %0, %1, %2;" : "=l"(r) : "l"(a), "l"(b)); return r;
}
__device__ __forceinline__ u64 add2(u64 a, u64 b) {
    u64 r; asm("add.rn.f32x2 %0, %1, %2;" : "=l"(r) : "l"(a), "l"(b)); return r;
}
__device__ __forceinline__ float ex2a(float x) {
    float r; asm("ex2.approx.f32 %0, %1;" : "=f"(r) : "f"(x)); return r;
}
__device__ __forceinline__ float sina(float x) {
    float r; asm("sin.approx.f32 %0, %1;" : "=f"(r) : "f"(x)); return r;
}
__device__ __forceinline__ float cosa(float x) {
    float r; asm("cos.approx.f32 %0, %1;" : "=f"(r) : "f"(x)); return r;
}
static __device__ __forceinline__ u64 SGN2() { return 0x8000000080000000ULL; }

// bf16x2 pack: low half = a, high half = b
__device__ __forceinline__ u32 pk_bf(float a, float b) {
    u32 r; asm("cvt.rn.satfinite.bf16x2.f32 %0, %1, %2;" : "=r"(r) : "f"(b), "f"(a));
    return r;
}
// split (x, y) into bf16x2 hi word + bf16x2 residual word
__device__ __forceinline__ void split_pair(float x, float y, u32& hi, u32& lo) {
    u32 hb = pk_bf(x, y);
    float xh = __uint_as_float(hb << 16);
    float yh = __uint_as_float(hb & 0xFFFF0000u);
    lo = pk_bf(x - xh, y - yh);
    hi = hb;
}

// D(16x8,f32) += A(16x16,bf16 row) * B(16x8,bf16 col)
__device__ __forceinline__ void mma_bf16(float& d0, float& d1, float& d2, float& d3,
                                         u32 a0, u32 a1, u32 a2, u32 a3,
                                         u32 b0, u32 b1) {
    asm volatile(
        "mma.sync.aligned.m16n8k16.row.col.f32.bf16.bf16.f32 "
        "{%0,%1,%2,%3}, {%4,%5,%6,%7}, {%8,%9}, {%0,%1,%2,%3};"
        : "+f"(d0), "+f"(d1), "+f"(d2), "+f"(d3)
        : "r"(a0), "r"(a1), "r"(a2), "r"(a3), "r"(b0), "r"(b1));
}

// Packed mag/phase: pr = mag*cos, pi = mag*sin for two modes at l0.
__device__ __forceinline__ void zpow2(
    u64 dreL2, u64 dim2, u64 l0f2,
    u64 nINV2PI2, u64 MAGIC2, u64 nMAGIC2, u64 PI2HI2, u64 PI2MID2,
    u64& pr2o, u64& pi2o)
{
    u64 m2 = mul2(dreL2, l0f2);
    float m0, m1; upk2(m2, m0, m1);
    float mag0 = ex2a(m0), mag1 = ex2a(m1);

    u64 p2   = mul2(dim2, l0f2);
    u64 e2   = fma2(dim2, l0f2, p2 ^ SGN2());     // exact residual of dim*l0
    u64 nk2  = fma2(p2, nINV2PI2, MAGIC2);
    u64 nkf2 = add2(nk2, nMAGIC2);                // -rint(p/2pi)
    u64 r2   = fma2(nkf2, PI2HI2, p2);
    r2       = add2(r2, fma2(nkf2, PI2MID2, e2));
    float r0, r1; upk2(r2, r0, r1);
    float s0 = sina(r0), c0 = cosa(r0);
    float s1 = sina(r1), c1 = cosa(r1);
    u64 mag2 = pk2(mag0, mag1);
    pr2o = mul2(mag2, pk2(c0, c1));
    pi2o = mul2(mag2, pk2(s0, s1));
}

__global__ __launch_bounds__(kTPB, 4) void s4d_kernel(
    const float* __restrict__ log_dt,
    const float* __restrict__ C_real,
    const float* __restrict__ C_imag,
    const float* __restrict__ log_A_real,
    const float* __restrict__ A_imag,
    float* __restrict__ out)
{
    __shared__ float Pdre[kN2], Pdim[kN2], Pctr[kN2], Pcti[kN2];
    __shared__ float PE8r[kN2], PE8i[kN2];
    __shared__ u32 tabh[32 * TABS], tabl[32 * TABS];

    const int h   = blockIdx.x;
    const int tid = threadIdx.x;
    const int wid = tid >> 5;
    const int lid = tid & 31;
    const int g   = lid >> 2;     // fragment group (0..7)
    const int t   = lid & 3;      // thread-in-group (0..3)

    const float INV2PI  = 0.15915494309189535f;
    const float PI2HI   = 6.28318548202514648f;   // fp32(2*pi)
    const float PI2MID  = -1.74845600e-7f;        // 2*pi - PI2HI
    const float MAGIC   = 12582912.0f;            // 1.5 * 2^23

    // ---- mode params + E8 = z^256 ----
    if (tid < kN2) {
        const int n = tid;
        const float LOG2E = 1.44269504088896341f;
        float dt  = __expf(log_dt[h]);
        float Are = -__expf(log_A_real[h * kN2 + n]);
        float Aim = A_imag[h * kN2 + n];
        float dre = Are * dt;
        float dim = Aim * dt;
        float er  = __expf(dre);
        float sn, cs;
        __sincosf(dim, &sn, &cs);
        float wr = er * cs, wi = er * sn;
        float e1r = wr - 1.0f, e1i = wi;
        float cr = C_real[h * kN2 + n], ci = C_imag[h * kN2 + n];
        float nr = cr * e1r - ci * e1i;
        float ni = cr * e1i + ci * e1r;
        float a2   = Are * Are + Aim * Aim;
        float inva = 2.0f / a2;                  // output factor 2 folded in
        Pdre[n] = dre * LOG2E;
        Pdim[n] = dim;
        Pctr[n] = (nr * Are + ni * Aim) * inva;
        Pcti[n] = (ni * Are - nr * Aim) * inva;
        // E8 = z^256 (dim*256 exact; Cody-Waite reduction, k <= ~410)
        float p256 = dim * 256.0f;
        float k8 = rintf(p256 * INV2PI);
        float r8 = fmaf(-k8, PI2HI, p256);
        r8 = fmaf(-k8, PI2MID, r8);
        float s8, c8;
        __sincosf(r8, &s8, &c8);
        float m8 = __expf(dre * 256.0f);
        PE8r[n] = m8 * c8;
        PE8i[n] = m8 * s8;
    }
    __syncthreads();

    const u64 nINV2PI2 = pk2(-INV2PI, -INV2PI);
    const u64 MAGIC2   = pk2(MAGIC, MAGIC);
    const u64 nMAGIC2  = pk2(-MAGIC, -MAGIC);
    const u64 PI2HI2   = pk2(PI2HI, PI2HI);
    const u64 PI2MID2  = pk2(PI2MID, PI2MID);

    // ---- B table: tab[j][n] = bf16x2{Re z_n^j, -Im z_n^j} (+ residual) ----
    {
        const int j  = tid & 31;
        const int ng = tid >> 5;                  // 4 mode-groups of 8
        const float jf = (float)j;
        const u64 jf2 = pk2(jf, jf);
        #pragma unroll
        for (int v = 0; v < 4; v++) {
            const int n0 = 8 * ng + 2 * v, n1 = n0 + 1;
            u64 dre2 = pk2(Pdre[n0], Pdre[n1]);
            u64 dim2 = pk2(Pdim[n0], Pdim[n1]);
            u64 pr2, pi2;
            zpow2(dre2, dim2, jf2, nINV2PI2, MAGIC2, nMAGIC2, PI2HI2, PI2MID2,
                  pr2, pi2);
            float r0, r1, i0, i1;
            upk2(pr2, r0, r1);
            upk2(pi2, i0, i1);
            u32 hi, lo;
            split_pair(r0, -i0, hi, lo);
            tabh[j * TABS + n0] = hi; tabl[j * TABS + n0] = lo;
            split_pair(r1, -i1, hi, lo);
            tabh[j * TABS + n1] = hi; tabl[j * TABS + n1] = lo;
        }
    }

    // ---- A fragments: 1 zpow2 per kstep (row 32w+g), rows +8/+16/+24 by E8 chain ----
    u32 ah[2][4][4], al[2][4][4];   // [mtile][kstep][reg]
    {
        const int r0 = 32 * wid + g;
        const float l0f = (float)(32 * r0);
        const u64 l0f2 = pk2(l0f, l0f);
        #pragma unroll
        for (int ks = 0; ks < 4; ks++) {
            const int n0 = 8 * ks + t, n1 = n0 + 4;
            u64 dre2 = pk2(Pdre[n0], Pdre[n1]);
            u64 dim2 = pk2(Pdim[n0], Pdim[n1]);
            u64 ctr2 = pk2(Pctr[n0], Pctr[n1]);
            u64 cti2 = pk2(Pcti[n0], Pcti[n1]);
            u64 e8r2 = pk2(PE8r[n0], PE8r[n1]);
            u64 e8i2 = pk2(PE8i[n0], PE8i[n1]);

            u64 pr2, pi2;
            zpow2(dre2, dim2, l0f2, nINV2PI2, MAGIC2, nMAGIC2, PI2HI2, PI2MID2,
                  pr2, pi2);
            u64 qr2 = fma2(cti2, pi2 ^ SGN2(), mul2(ctr2, pr2));   // Ct * z^{l0}
            u64 qi2 = fma2(cti2, pr2,          mul2(ctr2, pi2));

            #pragma unroll
            for (int c = 0; c < 4; c++) {        // rows r0 + 8c
                const int mt = c >> 1, rh = c & 1;
                float qr0, qr1, qi0, qi1;
                upk2(qr2, qr0, qr1);
                upk2(qi2, qi0, qi1);
                split_pair(qr0, qi0, ah[mt][ks][0 + rh], al[mt][ks][0 + rh]);
                split_pair(qr1, qi1, ah[mt][ks][2 + rh], al[mt][ks][2 + rh]);
                if (c < 3) {                     // q *= E8  (z^256)
                    u64 nqr = fma2(qi2, e8i2 ^ SGN2(), mul2(qr2, e8r2));
                    u64 nqi = fma2(qi2, e8r2,          mul2(qr2, e8i2));
                    qr2 = nqr; qi2 = nqi;
                }
            }
        }
    }
    __syncthreads();

    // ---- main GEMM: per n-tile, 24 mma (4 ksteps x 2 mtiles x 3 products) ----
    #pragma unroll
    for (int jt = 0; jt < 4; jt++) {
        const int jr = (8 * jt + g) * TABS;
        u32 bh[8], bl[8];
        #pragma unroll
        for (int ks = 0; ks < 4; ks++) {
            bh[2 * ks]     = tabh[jr + 8 * ks + t];
            bh[2 * ks + 1] = tabh[jr + 8 * ks + t + 4];
            bl[2 * ks]     = tabl[jr + 8 * ks + t];
            bl[2 * ks + 1] = tabl[jr + 8 * ks + t + 4];
        }
        float dA[2][4] = {{0,0,0,0},{0,0,0,0}};
        float dB[2][4] = {{0,0,0,0},{0,0,0,0}};
        #pragma unroll
        for (int ks = 0; ks < 4; ks++) {
            #pragma unroll
            for (int mt = 0; mt < 2; mt++) {
                float* d = (ks & 1) ? dB[mt] : dA[mt];
                mma_bf16(d[0], d[1], d[2], d[3],
                         ah[mt][ks][0], ah[mt][ks][1], ah[mt][ks][2], ah[mt][ks][3],
                         bh[2 * ks], bh[2 * ks + 1]);
                mma_bf16(d[0], d[1], d[2], d[3],
                         ah[mt][ks][0], ah[mt][ks][1], ah[mt][ks][2], ah[mt][ks][3],
                         bl[2 * ks], bl[2 * ks + 1]);
                mma_bf16(d[0], d[1], d[2], d[3],
                         al[mt][ks][0], al[mt][ks][1], al[mt][ks][2], al[mt][ks][3],
                         bh[2 * ks], bh[2 * ks + 1]);
            }
        }
        #pragma unroll
        for (int mt = 0; mt < 2; mt++) {
            const int m0 = 32 * wid + 16 * mt + g;
            float* op = out + (size_t)h * kL + 8 * jt + 2 * t;
            float2 v0, v1;
            v0.x = dA[mt][0] + dB[mt][0];
            v0.y = dA[mt][1] + dB[mt][1];
            v1.x = dA[mt][2] + dB[mt][2];
            v1.y = dA[mt][3] + dB[mt][3];
            *(float2*)(op + 32 * m0)       = v0;
            *(float2*)(op + 32 * (m0 + 8)) = v1;
        }
    }
}

extern "C" void kernel_launch(void* const* d_in, const int* in_sizes, int n_in,
                              void* d_out, int out_size) {
    const float* log_dt     = (const float*)d_in[0];
    const float* C_real     = (const float*)d_in[1];
    const float* C_imag     = (const float*)d_in[2];
    const float* log_A_real = (const float*)d_in[3];
    const float* A_imag     = (const float*)d_in[4];
    float* out = (float*)d_out;

    s4d_kernel<<<kH, kTPB>>>(log_dt, C_real, C_imag, log_A_real, A_imag, out);
}